// round 1
// baseline (speedup 1.0000x reference)
#include <cuda_runtime.h>

#define VOCAB  200000
#define DIM    128
#define NPOS   10
#define NNEG   64
#define NROWS  (1 + NPOS + NNEG)   // 75
#define VEC_PER_ROW (VOCAB / 4)    // 50000

// Scratch for recovered one-hot indices (alloc-free rule: __device__ global).
__device__ int g_idx[NROWS];

// ---------------------------------------------------------------------------
// Kernel A: stream the one-hot arrays (60 MB total), find nonzero column per
// row. Exactly one nonzero per row -> plain store, no atomics.
// ---------------------------------------------------------------------------
__global__ void skipgram_find_idx(const float4* __restrict__ center,
                                  const float4* __restrict__ pos,
                                  const float4* __restrict__ neg) {
    const long total = (long)NROWS * VEC_PER_ROW;   // 3.75M float4
    for (long i = (long)blockIdx.x * blockDim.x + threadIdx.x; i < total;
         i += (long)gridDim.x * blockDim.x) {
        int row = (int)(i / VEC_PER_ROW);
        int vv  = (int)(i - (long)row * VEC_PER_ROW);

        const float4* base;
        long off;
        if (row == 0)        { base = center; off = vv; }
        else if (row <= NPOS){ base = pos;    off = (long)(row - 1) * VEC_PER_ROW + vv; }
        else                 { base = neg;    off = (long)(row - 1 - NPOS) * VEC_PER_ROW + vv; }

        float4 x = base[off];
        // Branches almost never taken; no divergence cost in the common path.
        if (x.x != 0.0f) g_idx[row] = 4 * vv + 0;
        if (x.y != 0.0f) g_idx[row] = 4 * vv + 1;
        if (x.z != 0.0f) g_idx[row] = 4 * vv + 2;
        if (x.w != 0.0f) g_idx[row] = 4 * vv + 3;
    }
}

// Numerically stable log_sigmoid(x) = -softplus(-x)
__device__ __forceinline__ float log_sigmoidf(float x) {
    return (x >= 0.0f) ? -log1pf(expf(-x)) : (x - log1pf(expf(x)));
}

// ---------------------------------------------------------------------------
// Kernel B: one block, 256 threads (8 warps).
//   v = input_embeddings[:, c]                      (column gather, strided)
//   pos scores: dot(v, input_embeddings[:, p_i])    -> sum log_sigmoid(s)
//   neg scores: dot(v, output_embeddings[n_k, :])   -> sum log_sigmoid(-s)
//   out = -(pos_sum + neg_sum)
// ---------------------------------------------------------------------------
__global__ void skipgram_score(const float* __restrict__ inE,   // [DIM, VOCAB]
                               const float* __restrict__ outE,  // [VOCAB, DIM]
                               float* __restrict__ out) {
    __shared__ float v[DIM];
    __shared__ float partial[8];

    const int tid  = threadIdx.x;
    const int wid  = tid >> 5;
    const int lane = tid & 31;

    const int c = g_idx[0];
    if (tid < DIM) v[tid] = inE[(long)tid * VOCAB + c];
    __syncthreads();

    float acc = 0.0f;
    // 8 warps stride over the 74 context words -> memory-parallel gathers.
    for (int w = wid; w < NPOS + NNEG; w += 8) {
        const int idx = g_idx[1 + w];
        float dot = 0.0f;
        if (w < NPOS) {
            // column of inE (stride VOCAB)
            #pragma unroll
            for (int j = 0; j < DIM / 32; j++) {
                int d = lane + 32 * j;
                dot += v[d] * inE[(long)d * VOCAB + idx];
            }
        } else {
            // contiguous row of outE
            const float* r = outE + (long)idx * DIM;
            #pragma unroll
            for (int j = 0; j < DIM / 32; j++) {
                int d = lane + 32 * j;
                dot += v[d] * r[d];
            }
        }
        #pragma unroll
        for (int s = 16; s; s >>= 1) dot += __shfl_xor_sync(0xFFFFFFFFu, dot, s);
        if (lane == 0) {
            float x = (w < NPOS) ? dot : -dot;
            acc += log_sigmoidf(x);
        }
    }
    if (lane == 0) partial[wid] = acc;
    __syncthreads();
    if (tid == 0) {
        float s = 0.0f;
        #pragma unroll
        for (int i = 0; i < 8; i++) s += partial[i];
        *out = -s;
    }
}

extern "C" void kernel_launch(void* const* d_in, const int* in_sizes, int n_in,
                              void* d_out, int out_size) {
    const float* center = (const float*)d_in[0];   // [VOCAB]
    const float* pos    = (const float*)d_in[1];   // [NPOS, VOCAB]
    const float* neg    = (const float*)d_in[2];   // [NNEG, VOCAB]
    const float* inE    = (const float*)d_in[3];   // [DIM, VOCAB]
    const float* outE   = (const float*)d_in[4];   // [VOCAB, DIM]
    float* out = (float*)d_out;

    const long total_vec = (long)NROWS * VEC_PER_ROW;          // 3,750,000
    const int threads = 256;
    int blocks = (int)((total_vec + threads - 1) / threads);   // ~14649

    skipgram_find_idx<<<blocks, threads>>>((const float4*)center,
                                           (const float4*)pos,
                                           (const float4*)neg);
    skipgram_score<<<1, 256>>>(inE, outE, out);
}

// round 2
// speedup vs baseline: 1.7578x; 1.7578x over previous
#include <cuda_runtime.h>

#define VOCAB  200000
#define DIM    128
#define NPOS   10
#define NNEG   64
#define NCTX   (NPOS + NNEG)       // 74
#define NROWS  (1 + NPOS + NNEG)   // 75
#define VEC_PER_ROW (VOCAB / 4)    // 50000

// Scratch for recovered one-hot indices (alloc-free rule: __device__ global).
__device__ int g_idx[NROWS];

// ---------------------------------------------------------------------------
// Kernel A: stream the one-hot arrays (60 MB), find nonzero column per row.
// 4 independent coalesced float4 streaming loads per thread. Also zero-inits
// the output scalar so kernel B can accumulate atomically.
// ---------------------------------------------------------------------------
#define BATCH 4
__global__ void skipgram_find_idx(const float4* __restrict__ center,
                                  const float4* __restrict__ pos,
                                  const float4* __restrict__ neg,
                                  float* __restrict__ out) {
    if (blockIdx.x == 0 && threadIdx.x == 0) *out = 0.0f;

    const long total = (long)NROWS * VEC_PER_ROW;   // 3,750,000 float4
    const long base  = (long)blockIdx.x * (blockDim.x * BATCH) + threadIdx.x;

    #pragma unroll
    for (int k = 0; k < BATCH; k++) {
        long i = base + (long)k * blockDim.x;
        if (i >= total) continue;
        int row = (int)(i / VEC_PER_ROW);
        int vv  = (int)(i - (long)row * VEC_PER_ROW);

        const float4* p;
        if (row == 0)         p = center + vv;
        else if (row <= NPOS) p = pos + (long)(row - 1) * VEC_PER_ROW + vv;
        else                  p = neg + (long)(row - 1 - NPOS) * VEC_PER_ROW + vv;

        float4 x = __ldcs(p);
        if (x.x != 0.0f) g_idx[row] = 4 * vv + 0;
        if (x.y != 0.0f) g_idx[row] = 4 * vv + 1;
        if (x.z != 0.0f) g_idx[row] = 4 * vv + 2;
        if (x.w != 0.0f) g_idx[row] = 4 * vv + 3;
    }
}

// Numerically stable log_sigmoid(x) = -softplus(-x)
__device__ __forceinline__ float log_sigmoidf(float x) {
    return (x >= 0.0f) ? -log1pf(expf(-x)) : (x - log1pf(expf(x)));
}

// ---------------------------------------------------------------------------
// Kernel B: 74 blocks x 128 threads, one context word per block.
// Two dependent memory rounds total:
//   round 1: load g_idx[0] and g_idx[1+w]
//   round 2: gather v[d] and u[d] in parallel (128 lanes)
// then block-reduce the dot and atomicAdd(-log_sigmoid(+/-dot)) into out.
// ---------------------------------------------------------------------------
__global__ void skipgram_score(const float* __restrict__ inE,   // [DIM, VOCAB]
                               const float* __restrict__ outE,  // [VOCAB, DIM]
                               float* __restrict__ out) {
    __shared__ float partial[4];

    const int w    = blockIdx.x;          // 0..73
    const int d    = threadIdx.x;         // 0..127
    const int wid  = d >> 5;
    const int lane = d & 31;

    const int c   = __ldg(&g_idx[0]);
    const int idx = __ldg(&g_idx[1 + w]);

    const float vd = inE[(long)d * VOCAB + c];
    const float ud = (w < NPOS) ? inE[(long)d * VOCAB + idx]
                                : outE[(long)idx * DIM + d];

    float dot = vd * ud;
    #pragma unroll
    for (int s = 16; s; s >>= 1) dot += __shfl_xor_sync(0xFFFFFFFFu, dot, s);
    if (lane == 0) partial[wid] = dot;
    __syncthreads();

    if (d == 0) {
        float t = partial[0] + partial[1] + partial[2] + partial[3];
        float x = (w < NPOS) ? t : -t;
        atomicAdd(out, -log_sigmoidf(x));
    }
}

extern "C" void kernel_launch(void* const* d_in, const int* in_sizes, int n_in,
                              void* d_out, int out_size) {
    const float* center = (const float*)d_in[0];   // [VOCAB]
    const float* pos    = (const float*)d_in[1];   // [NPOS, VOCAB]
    const float* neg    = (const float*)d_in[2];   // [NNEG, VOCAB]
    const float* inE    = (const float*)d_in[3];   // [DIM, VOCAB]
    const float* outE   = (const float*)d_in[4];   // [VOCAB, DIM]
    float* out = (float*)d_out;

    const long total_vec = (long)NROWS * VEC_PER_ROW;          // 3,750,000
    const int threads = 256;
    const int per_block = threads * BATCH;                     // 1024
    int blocks = (int)((total_vec + per_block - 1) / per_block); // 3663

    skipgram_find_idx<<<blocks, threads>>>((const float4*)center,
                                           (const float4*)pos,
                                           (const float4*)neg, out);
    skipgram_score<<<NCTX, DIM>>>(inE, outE, out);
}